// round 3
// baseline (speedup 1.0000x reference)
#include <cuda_runtime.h>
#include <math.h>

// ---------------- scratch (no allocation allowed -> __device__ globals) ----------------
__device__ float g_x1[512*32*30*30];     // conv1 out
__device__ float g_x2[512*64*14*14];     // conv2 out
__device__ float g_x3[512*32*12*12];     // conv3 out == fc input rows [512][4608]
__device__ float g_fc[512*512];          // fc out
__device__ float g_gi[512*1536];         // input-to-hidden gates
__device__ float g_whhT[512*1536];       // w_hh transposed [k][row]
__device__ float g_h[16*512];            // GRU hidden
__device__ float g_outs[512*512];        // GRU outputs per (t,n)
__device__ float g_part[8*16*1536];      // GRU k-split partials [ks][n][row]

// ---------------- conv1: [512,4,124,124] -> [512,32,30,30], 8x8 s4 ----------------
__global__ void k_conv1(const float* __restrict__ in, const float* __restrict__ w,
                        const float* __restrict__ bias) {
    __shared__ __align__(16) float sW[8192];   // [ickykx 256][oc 32]
    __shared__ __align__(16) float sIn[3968];  // [ic 4][ky 8][x 124]
    int n = blockIdx.x;
    int tid = threadIdx.x, lane = tid & 31, wrp = tid >> 5;   // lane=oc, wrp=ox group
    for (int i = tid; i < 8192; i += 256) {
        int oc = i >> 8, idx = i & 255;
        sW[idx*32 + oc] = w[i];
    }
    const float* inN = in + (size_t)n*4*124*124;
    float bv = bias[lane];
    const float inv255 = 1.f/255.f;
    for (int oy = 0; oy < 30; oy++) {
        __syncthreads();
        for (int i = tid; i < 3968; i += 256) {
            int c = i / 992; int rem = i - c*992;
            int r = rem / 124; int x = rem - r*124;
            sIn[i] = inN[c*15376 + (4*oy + r)*124 + x];
        }
        __syncthreads();
        float acc0=0.f, acc1=0.f, acc2=0.f, acc3=0.f;
        #pragma unroll
        for (int ic = 0; ic < 4; ic++) {
            #pragma unroll
            for (int ky = 0; ky < 8; ky++) {
                const float* rowIn = &sIn[(ic*8+ky)*124];
                const float* wr = &sW[(ic*64+ky*8)*32 + lane];
                float w0=wr[0],w1=wr[32],w2=wr[64],w3=wr[96],
                      w4=wr[128],w5=wr[160],w6=wr[192],w7=wr[224];
                const float4* p = (const float4*)(rowIn + 4*wrp);
                float4 a = p[0], b2 = p[1];
                acc0 += w0*a.x+w1*a.y+w2*a.z+w3*a.w+w4*b2.x+w5*b2.y+w6*b2.z+w7*b2.w;
                a = p[8]; b2 = p[9];
                acc1 += w0*a.x+w1*a.y+w2*a.z+w3*a.w+w4*b2.x+w5*b2.y+w6*b2.z+w7*b2.w;
                a = p[16]; b2 = p[17];
                acc2 += w0*a.x+w1*a.y+w2*a.z+w3*a.w+w4*b2.x+w5*b2.y+w6*b2.z+w7*b2.w;
                if (wrp < 6) {
                    a = p[24]; b2 = p[25];
                    acc3 += w0*a.x+w1*a.y+w2*a.z+w3*a.w+w4*b2.x+w5*b2.y+w6*b2.z+w7*b2.w;
                }
            }
        }
        __syncthreads();
        // stage: [oc][ox 30]
        sIn[lane*30 + wrp]      = fmaxf(acc0*inv255 + bv, 0.f);
        sIn[lane*30 + wrp + 8]  = fmaxf(acc1*inv255 + bv, 0.f);
        sIn[lane*30 + wrp + 16] = fmaxf(acc2*inv255 + bv, 0.f);
        if (wrp < 6) sIn[lane*30 + wrp + 24] = fmaxf(acc3*inv255 + bv, 0.f);
        __syncthreads();
        float* outp = g_x1 + (size_t)n*28800 + oy*30;
        for (int i = tid; i < 960; i += 256) {
            int oc = i / 30, ox = i - oc*30;
            outp[oc*900 + ox] = sIn[i];
        }
    }
}

// ---------------- conv2: [512,32,30,30] -> [512,64,14,14], 4x4 s2 ----------------
__global__ void k_conv2(const float* __restrict__ w, const float* __restrict__ bias) {
    extern __shared__ float sm2[];
    float* sW  = sm2;            // 16384 : [ickykx 512][oc 32]
    float* sIn = sm2 + 16384;    // 3840  : [ic 32][r 4][x 30]
    int n = blockIdx.x, h = blockIdx.y;          // h = oc half
    int tid = threadIdx.x, lane = tid & 31, wrp = tid >> 5;  // 7 warps, lane=oc, wrp=ox grp
    for (int i = tid; i < 16384; i += 224) {
        int oc = i >> 9, idx = i & 511;
        sW[idx*32 + oc] = w[(h*32+oc)*512 + idx];
    }
    float bv = bias[h*32 + lane];
    const float* src = g_x1 + (size_t)n*28800;
    float* dstBase = g_x2 + (size_t)(n*64 + h*32)*196;
    for (int oy = 0; oy < 14; oy++) {
        __syncthreads();
        for (int i = tid; i < 3840; i += 224) {
            int ic = i / 120; int rem = i - ic*120;
            int r = rem / 30; int x = rem - r*30;
            sIn[i] = src[ic*900 + (2*oy+r)*30 + x];
        }
        __syncthreads();
        float acc0 = 0.f, acc1 = 0.f;
        #pragma unroll 4
        for (int ic = 0; ic < 32; ic++) {
            #pragma unroll
            for (int ky = 0; ky < 4; ky++) {
                const float* rowIn = &sIn[(ic*4+ky)*30];
                const float* wr = &sW[(ic*16+ky*4)*32 + lane];
                float w0=wr[0], w1=wr[32], w2=wr[64], w3=wr[96];
                float2 f0 = *(const float2*)(rowIn + 2*wrp);
                float2 f1 = *(const float2*)(rowIn + 2*wrp + 2);
                acc0 += w0*f0.x + w1*f0.y + w2*f1.x + w3*f1.y;
                f0 = *(const float2*)(rowIn + 2*wrp + 14);
                f1 = *(const float2*)(rowIn + 2*wrp + 16);
                acc1 += w0*f0.x + w1*f0.y + w2*f1.x + w3*f1.y;
            }
        }
        __syncthreads();
        sIn[lane*14 + wrp]     = fmaxf(acc0 + bv, 0.f);
        sIn[lane*14 + wrp + 7] = fmaxf(acc1 + bv, 0.f);
        __syncthreads();
        for (int i = tid; i < 448; i += 224) {
            int oc = i / 14, ox = i - oc*14;
            dstBase[oc*196 + oy*14 + ox] = sIn[i];
        }
    }
}

// ---------------- conv3: [512,64,14,14] -> [512,32,12,12], 3x3 s1 ----------------
__global__ void k_conv3(const float* __restrict__ w, const float* __restrict__ bias) {
    extern __shared__ float sm3[];
    float* sW  = sm3;            // 18432 : [icky kx 576][oc 32]
    float* sIn = sm3 + 18432;    // 12544 : [ic 64][y 14][x 14]
    int n = blockIdx.x;
    int tid = threadIdx.x, lane = tid & 31, oy = tid >> 5;   // 12 warps, lane=oc, warp=oy
    for (int i = tid; i < 18432; i += 384) {
        int oc = i / 576, idx = i - oc*576;
        sW[idx*32 + oc] = w[i];
    }
    const float* src = g_x2 + (size_t)n*12544;
    for (int i = tid; i < 12544; i += 384) sIn[i] = src[i];
    __syncthreads();
    float acc[12];
    #pragma unroll
    for (int ox = 0; ox < 12; ox++) acc[ox] = 0.f;
    for (int ic = 0; ic < 64; ic++) {
        #pragma unroll
        for (int ky = 0; ky < 3; ky++) {
            const float* rowIn = &sIn[ic*196 + (oy+ky)*14];
            const float* wr = &sW[(ic*9+ky*3)*32 + lane];
            float w0 = wr[0], w1 = wr[32], w2 = wr[64];
            float r[14];
            #pragma unroll
            for (int x = 0; x < 14; x++) r[x] = rowIn[x];
            #pragma unroll
            for (int ox = 0; ox < 12; ox++)
                acc[ox] += w0*r[ox] + w1*r[ox+1] + w2*r[ox+2];
        }
    }
    float bv = bias[lane];
    __syncthreads();
    #pragma unroll
    for (int ox = 0; ox < 12; ox++)
        sIn[lane*144 + oy*12 + ox] = fmaxf(acc[ox] + bv, 0.f);
    __syncthreads();
    float* dst = g_x3 + (size_t)n*4608;
    for (int i = tid; i < 4608; i += 384) dst[i] = sIn[i];
}

// ---------------- generic GEMM: C = act(A[M,K] * B[N,K]^T + bias) ----------------
// MODE 0: fc  (A=g_x3, C=g_fc,  M=512,N=512, K=4608, relu)
// MODE 1: gi  (A=g_fc, C=g_gi,  M=512,N=1536,K=512,  none)
template<int MODE>
__global__ void k_gemm(const float* __restrict__ Bm, const float* __restrict__ bias) {
    const int N = (MODE==0) ? 512 : 1536;
    const int K = (MODE==0) ? 4608 : 512;
    const float* A = (MODE==0) ? g_x3 : g_fc;
    float* C = (MODE==0) ? g_fc : g_gi;
    __shared__ float As[64*17];
    __shared__ float Bs[32*17];
    int tid = threadIdx.x;
    int tx = tid & 7, ty = tid >> 3;   // 8 x 16
    int n0 = blockIdx.x*32, m0 = blockIdx.y*64;
    float acc[4][4];
    #pragma unroll
    for (int i = 0; i < 4; i++)
        #pragma unroll
        for (int j = 0; j < 4; j++) acc[i][j] = 0.f;
    for (int k0 = 0; k0 < K; k0 += 16) {
        __syncthreads();
        for (int i = tid; i < 1024; i += 128) {
            int m = i >> 4, kk = i & 15;
            As[m*17+kk] = A[(size_t)(m0+m)*K + k0 + kk];
        }
        for (int i = tid; i < 512; i += 128) {
            int nn = i >> 4, kk = i & 15;
            Bs[nn*17+kk] = Bm[(size_t)(n0+nn)*K + k0 + kk];
        }
        __syncthreads();
        #pragma unroll
        for (int kk = 0; kk < 16; kk++) {
            float a[4], b[4];
            #pragma unroll
            for (int i = 0; i < 4; i++) a[i] = As[(ty*4+i)*17 + kk];
            #pragma unroll
            for (int j = 0; j < 4; j++) b[j] = Bs[(tx*4+j)*17 + kk];
            #pragma unroll
            for (int i = 0; i < 4; i++)
                #pragma unroll
                for (int j = 0; j < 4; j++) acc[i][j] += a[i]*b[j];
        }
    }
    #pragma unroll
    for (int i = 0; i < 4; i++) {
        int m = m0 + ty*4 + i;
        #pragma unroll
        for (int j = 0; j < 4; j++) {
            int nn = n0 + tx*4 + j;
            float v = acc[i][j] + bias[nn];
            if (MODE == 0) v = fmaxf(v, 0.f);
            C[(size_t)m*N + nn] = v;
        }
    }
}

// ---------------- GRU helpers ----------------
__global__ void k_transpose(const float* __restrict__ w_hh) {
    int i = blockIdx.x*256 + threadIdx.x;   // < 786432
    int r = i >> 9, k = i & 511;
    g_whhT[k*1536 + r] = w_hh[i];
}

__global__ void k_init_h(const float* __restrict__ states) {
    int i = blockIdx.x*256 + threadIdx.x;   // < 8192
    g_h[i] = states[i];
}

// partial gh: grid (6 rchunk, 8 ksplit), 256 thr.  g_part[ks][n][r]
__global__ void k_gru_gemm(const float* __restrict__ masks, int t) {
    __shared__ __align__(16) float sH[1024];   // [kk 64][n 16]
    int tid = threadIdx.x;
    int r = blockIdx.x*256 + tid;
    int k0 = blockIdx.y*64;
    for (int i = tid; i < 1024; i += 256) {
        int kk = i >> 4, n = i & 15;
        sH[i] = g_h[n*512 + k0 + kk] * masks[t*16 + n];
    }
    __syncthreads();
    float acc[16];
    #pragma unroll
    for (int n = 0; n < 16; n++) acc[n] = 0.f;
    const float* wp = g_whhT + (size_t)k0*1536 + r;
    #pragma unroll 4
    for (int kk = 0; kk < 64; kk++) {
        float wv = wp[(size_t)kk*1536];
        const float4* hp = (const float4*)&sH[kk*16];
        float4 h0 = hp[0], h1 = hp[1], h2 = hp[2], h3 = hp[3];
        acc[0]+=wv*h0.x;  acc[1]+=wv*h0.y;  acc[2]+=wv*h0.z;  acc[3]+=wv*h0.w;
        acc[4]+=wv*h1.x;  acc[5]+=wv*h1.y;  acc[6]+=wv*h1.z;  acc[7]+=wv*h1.w;
        acc[8]+=wv*h2.x;  acc[9]+=wv*h2.y;  acc[10]+=wv*h2.z; acc[11]+=wv*h2.w;
        acc[12]+=wv*h3.x; acc[13]+=wv*h3.y; acc[14]+=wv*h3.z; acc[15]+=wv*h3.w;
    }
    float* pp = g_part + (size_t)blockIdx.y*16*1536 + r;
    #pragma unroll
    for (int n = 0; n < 16; n++) pp[n*1536] = acc[n];
}

// reduce + gates + state update. grid 32, 256 thr.
__global__ void k_gru_gate(const float* __restrict__ masks, const float* __restrict__ b_hh, int t) {
    int idx = blockIdx.x*256 + threadIdx.x;    // < 8192
    int n = idx >> 9, hh = idx & 511;
    int row = t*16 + n;
    float sr = b_hh[hh], sz = b_hh[512+hh], sn = b_hh[1024+hh];
    #pragma unroll
    for (int ks = 0; ks < 8; ks++) {
        const float* p = g_part + (size_t)(ks*16+n)*1536;
        sr += p[hh]; sz += p[512+hh]; sn += p[1024+hh];
    }
    const float* gi = g_gi + (size_t)row*1536;
    float rg = 1.f/(1.f + expf(-(gi[hh] + sr)));
    float zg = 1.f/(1.f + expf(-(gi[512+hh] + sz)));
    float ng = tanhf(gi[1024+hh] + rg*sn);
    float hm = g_h[n*512+hh] * masks[row];
    float hnew = (1.f - zg)*ng + zg*hm;
    g_h[n*512+hh] = hnew;
    g_outs[(size_t)row*512 + hh] = hnew;
}

// ---------------- heads: warp per row ----------------
__global__ void k_heads(const float* __restrict__ aw, const float* __restrict__ ab,
                        const float* __restrict__ cw, const float* __restrict__ cb,
                        const int* __restrict__ action, float* __restrict__ out) {
    int wrp = threadIdx.x >> 5, lane = threadIdx.x & 31;
    int row = blockIdx.x*4 + wrp;
    const float* x = g_outs + (size_t)row*512;
    float p[7];
    #pragma unroll
    for (int j = 0; j < 7; j++) p[j] = 0.f;
    for (int k = lane; k < 512; k += 32) {
        float xv = x[k];
        #pragma unroll
        for (int j = 0; j < 6; j++) p[j] += xv * aw[j*512 + k];
        p[6] += xv * cw[k];
    }
    #pragma unroll
    for (int j = 0; j < 7; j++)
        #pragma unroll
        for (int o = 16; o > 0; o >>= 1) p[j] += __shfl_xor_sync(0xffffffffu, p[j], o);
    if (lane == 0) {
        float l[6];
        #pragma unroll
        for (int j = 0; j < 6; j++) l[j] = p[j] + ab[j];
        float v = p[6] + cb[0];
        float m = l[0];
        #pragma unroll
        for (int j = 1; j < 6; j++) m = fmaxf(m, l[j]);
        float se = 0.f;
        #pragma unroll
        for (int j = 0; j < 6; j++) se += expf(l[j] - m);
        float lse = m + logf(se);
        int a = action[row];
        float alp = 0.f;
        #pragma unroll
        for (int j = 0; j < 6; j++) if (j == a) alp = l[j] - lse;
        float ent = 0.f;
        #pragma unroll
        for (int j = 0; j < 6; j++) { float lp = l[j] - lse; ent -= expf(lp)*lp; }
        out[row] = v;
        out[512 + row] = alp;
        out[1024 + row] = ent;
    }
}

__global__ void k_states_out(float* __restrict__ out) {
    int i = blockIdx.x*256 + threadIdx.x;   // < 8192
    out[1536 + i] = g_h[i];
}

// ---------------- launch ----------------
extern "C" void kernel_launch(void* const* d_in, const int* in_sizes, int n_in,
                              void* d_out, int out_size) {
    const float* inputs   = (const float*)d_in[0];
    const float* states   = (const float*)d_in[1];
    const float* masks    = (const float*)d_in[2];
    const int*   action   = (const int*)d_in[3];     // JAX default: int64 demoted to int32
    const float* conv1_w  = (const float*)d_in[4];
    const float* conv1_b  = (const float*)d_in[5];
    const float* conv2_w  = (const float*)d_in[6];
    const float* conv2_b  = (const float*)d_in[7];
    const float* conv3_w  = (const float*)d_in[8];
    const float* conv3_b  = (const float*)d_in[9];
    const float* fc_w     = (const float*)d_in[10];
    const float* fc_b     = (const float*)d_in[11];
    const float* w_ih     = (const float*)d_in[12];
    const float* w_hh     = (const float*)d_in[13];
    const float* b_ih     = (const float*)d_in[14];
    const float* b_hh     = (const float*)d_in[15];
    const float* actor_w  = (const float*)d_in[16];
    const float* actor_b  = (const float*)d_in[17];
    const float* critic_w = (const float*)d_in[18];
    const float* critic_b = (const float*)d_in[19];
    float* out = (float*)d_out;
    (void)in_sizes; (void)n_in; (void)out_size;

    cudaFuncSetAttribute(k_conv2, cudaFuncAttributeMaxDynamicSharedMemorySize, 80896);
    cudaFuncSetAttribute(k_conv3, cudaFuncAttributeMaxDynamicSharedMemorySize, 123904);

    k_conv1<<<512, 256>>>(inputs, conv1_w, conv1_b);
    k_conv2<<<dim3(512, 2), 224, 80896>>>(conv2_w, conv2_b);
    k_conv3<<<512, 384, 123904>>>(conv3_w, conv3_b);
    k_gemm<0><<<dim3(16, 8), 128>>>(fc_w, fc_b);     // fc (relu)
    k_gemm<1><<<dim3(48, 8), 128>>>(w_ih, b_ih);     // gi
    k_transpose<<<3072, 256>>>(w_hh);
    k_init_h<<<32, 256>>>(states);
    for (int t = 0; t < 32; t++) {
        k_gru_gemm<<<dim3(6, 8), 256>>>(masks, t);
        k_gru_gate<<<32, 256>>>(masks, b_hh, t);
    }
    k_heads<<<128, 128>>>(actor_w, actor_b, critic_w, critic_b, action, out);
    k_states_out<<<32, 256>>>(out);
}

// round 4
// speedup vs baseline: 1.2824x; 1.2824x over previous
#include <cuda_runtime.h>
#include <math.h>

typedef unsigned long long ULL;

// ---------------- scratch ----------------
__device__ float g_x1[512*32*30*30];     // conv1 out
__device__ float g_x2[512*64*14*14];     // conv2 out
__device__ float g_x3[512*32*12*12];     // conv3 out == fc input rows [512][4608]
__device__ float g_fc[512*512];          // fc out
__device__ float g_gi[512*1536];         // input-to-hidden gates
__device__ float g_h[16*512];            // GRU hidden
__device__ float g_outs[512*512];        // GRU outputs per (t,n)
__device__ float g_red[8*512*512];       // split-K partials
__device__ int   g_bar;                  // GRU grid barrier counter

// ---------------- f32x2 helpers ----------------
__device__ __forceinline__ ULL ffma2(ULL a, ULL b, ULL c) {
    ULL d;
    asm("fma.rn.f32x2 %0, %1, %2, %3;" : "=l"(d) : "l"(a), "l"(b), "l"(c));
    return d;
}
__device__ __forceinline__ float2 unpack2(ULL a) {
    float2 u;
    asm("mov.b64 {%0, %1}, %2;" : "=f"(u.x), "=f"(u.y) : "l"(a));
    return u;
}

// ---------------- conv1: [512,4,124,124] -> [512,32,30,30], 8x8 s4 ----------------
__global__ void k_conv1(const float* __restrict__ in, const float* __restrict__ w,
                        const float* __restrict__ bias) {
    __shared__ __align__(16) float sW[8192];   // [ickykx 256][oc 32]
    __shared__ __align__(16) float sIn[3968];  // [ic 4][ky 8][x 124]
    int n = blockIdx.x;
    int tid = threadIdx.x, lane = tid & 31, wrp = tid >> 5;
    for (int i = tid; i < 8192; i += 256) {
        int oc = i >> 8, idx = i & 255;
        sW[idx*32 + oc] = w[i];
    }
    const float* inN = in + (size_t)n*4*124*124;
    float bv = bias[lane];
    const float inv255 = 1.f/255.f;
    for (int oy = 0; oy < 30; oy++) {
        __syncthreads();
        for (int i = tid; i < 3968; i += 256) {
            int c = i / 992; int rem = i - c*992;
            int r = rem / 124; int x = rem - r*124;
            sIn[i] = inN[c*15376 + (4*oy + r)*124 + x];
        }
        __syncthreads();
        float acc0=0.f, acc1=0.f, acc2=0.f, acc3=0.f;
        #pragma unroll
        for (int ic = 0; ic < 4; ic++) {
            #pragma unroll
            for (int ky = 0; ky < 8; ky++) {
                const float* rowIn = &sIn[(ic*8+ky)*124];
                const float* wr = &sW[(ic*64+ky*8)*32 + lane];
                float w0=wr[0],w1=wr[32],w2=wr[64],w3=wr[96],
                      w4=wr[128],w5=wr[160],w6=wr[192],w7=wr[224];
                const float4* p = (const float4*)(rowIn + 4*wrp);
                float4 a = p[0], b2 = p[1];
                acc0 += w0*a.x+w1*a.y+w2*a.z+w3*a.w+w4*b2.x+w5*b2.y+w6*b2.z+w7*b2.w;
                a = p[8]; b2 = p[9];
                acc1 += w0*a.x+w1*a.y+w2*a.z+w3*a.w+w4*b2.x+w5*b2.y+w6*b2.z+w7*b2.w;
                a = p[16]; b2 = p[17];
                acc2 += w0*a.x+w1*a.y+w2*a.z+w3*a.w+w4*b2.x+w5*b2.y+w6*b2.z+w7*b2.w;
                if (wrp < 6) {
                    a = p[24]; b2 = p[25];
                    acc3 += w0*a.x+w1*a.y+w2*a.z+w3*a.w+w4*b2.x+w5*b2.y+w6*b2.z+w7*b2.w;
                }
            }
        }
        __syncthreads();
        sIn[lane*30 + wrp]      = fmaxf(acc0*inv255 + bv, 0.f);
        sIn[lane*30 + wrp + 8]  = fmaxf(acc1*inv255 + bv, 0.f);
        sIn[lane*30 + wrp + 16] = fmaxf(acc2*inv255 + bv, 0.f);
        if (wrp < 6) sIn[lane*30 + wrp + 24] = fmaxf(acc3*inv255 + bv, 0.f);
        __syncthreads();
        float* outp = g_x1 + (size_t)n*28800 + oy*30;
        for (int i = tid; i < 960; i += 256) {
            int oc = i / 30, ox = i - oc*30;
            outp[oc*900 + ox] = sIn[i];
        }
    }
}

// ---------------- conv2: [512,32,30,30] -> [512,64,14,14], 4x4 s2 ----------------
__global__ void k_conv2(const float* __restrict__ w, const float* __restrict__ bias) {
    extern __shared__ float sm2[];
    float* sW  = sm2;            // 16384
    float* sIn = sm2 + 16384;    // 3840
    int n = blockIdx.x, h = blockIdx.y;
    int tid = threadIdx.x, lane = tid & 31, wrp = tid >> 5;
    for (int i = tid; i < 16384; i += 224) {
        int oc = i >> 9, idx = i & 511;
        sW[idx*32 + oc] = w[(h*32+oc)*512 + idx];
    }
    float bv = bias[h*32 + lane];
    const float* src = g_x1 + (size_t)n*28800;
    float* dstBase = g_x2 + (size_t)(n*64 + h*32)*196;
    for (int oy = 0; oy < 14; oy++) {
        __syncthreads();
        for (int i = tid; i < 3840; i += 224) {
            int ic = i / 120; int rem = i - ic*120;
            int r = rem / 30; int x = rem - r*30;
            sIn[i] = src[ic*900 + (2*oy+r)*30 + x];
        }
        __syncthreads();
        float acc0 = 0.f, acc1 = 0.f;
        #pragma unroll 4
        for (int ic = 0; ic < 32; ic++) {
            #pragma unroll
            for (int ky = 0; ky < 4; ky++) {
                const float* rowIn = &sIn[(ic*4+ky)*30];
                const float* wr = &sW[(ic*16+ky*4)*32 + lane];
                float w0=wr[0], w1=wr[32], w2=wr[64], w3=wr[96];
                float2 f0 = *(const float2*)(rowIn + 2*wrp);
                float2 f1 = *(const float2*)(rowIn + 2*wrp + 2);
                acc0 += w0*f0.x + w1*f0.y + w2*f1.x + w3*f1.y;
                f0 = *(const float2*)(rowIn + 2*wrp + 14);
                f1 = *(const float2*)(rowIn + 2*wrp + 16);
                acc1 += w0*f0.x + w1*f0.y + w2*f1.x + w3*f1.y;
            }
        }
        __syncthreads();
        sIn[lane*14 + wrp]     = fmaxf(acc0 + bv, 0.f);
        sIn[lane*14 + wrp + 7] = fmaxf(acc1 + bv, 0.f);
        __syncthreads();
        for (int i = tid; i < 448; i += 224) {
            int oc = i / 14, ox = i - oc*14;
            dstBase[oc*196 + oy*14 + ox] = sIn[i];
        }
    }
}

// ---------------- conv3: [512,64,14,14] -> [512,32,12,12], 3x3 s1 ----------------
__global__ void k_conv3(const float* __restrict__ w, const float* __restrict__ bias) {
    extern __shared__ float sm3[];
    float* sW  = sm3;            // 18432
    float* sIn = sm3 + 18432;    // 12544
    int n = blockIdx.x;
    int tid = threadIdx.x, lane = tid & 31, oy = tid >> 5;
    for (int i = tid; i < 18432; i += 384) {
        int oc = i / 576, idx = i - oc*576;
        sW[idx*32 + oc] = w[i];
    }
    const float* src = g_x2 + (size_t)n*12544;
    for (int i = tid; i < 12544; i += 384) sIn[i] = src[i];
    __syncthreads();
    float acc[12];
    #pragma unroll
    for (int ox = 0; ox < 12; ox++) acc[ox] = 0.f;
    for (int ic = 0; ic < 64; ic++) {
        #pragma unroll
        for (int ky = 0; ky < 3; ky++) {
            const float* rowIn = &sIn[ic*196 + (oy+ky)*14];
            const float* wr = &sW[(ic*9+ky*3)*32 + lane];
            float w0 = wr[0], w1 = wr[32], w2 = wr[64];
            float r[14];
            #pragma unroll
            for (int x = 0; x < 14; x++) r[x] = rowIn[x];
            #pragma unroll
            for (int ox = 0; ox < 12; ox++)
                acc[ox] += w0*r[ox] + w1*r[ox+1] + w2*r[ox+2];
        }
    }
    float bv = bias[lane];
    __syncthreads();
    #pragma unroll
    for (int ox = 0; ox < 12; ox++)
        sIn[lane*144 + oy*12 + ox] = fmaxf(acc[ox] + bv, 0.f);
    __syncthreads();
    float* dst = g_x3 + (size_t)n*4608;
    for (int i = tid; i < 4608; i += 384) dst[i] = sIn[i];
}

// ---------------- split-K f32x2 GEMM ----------------
// C_partial[ks][m][n] = A[M,K] x B[N,K]^T over k-slice ks.
// grid: (N/64, M/128, S), block 256.  Tile 128m x 64n, microtile 8m x 4n.
template<int N, int K, int S>
__global__ void k_gemm2(const float* __restrict__ A, const float* __restrict__ Bm,
                        float* __restrict__ Cp) {
    const int KS = K / S;
    __shared__ __align__(16) float As[16*132];   // [k][m] transposed
    __shared__ __align__(16) float Bs[16*136];   // [k][2n] duplicated pairs
    int tid = threadIdx.x;
    int tx = tid & 15, ty = tid >> 4;
    int n0 = blockIdx.x*64, m0 = blockIdx.y*128, ks = blockIdx.z;
    int kbase = ks*KS;
    const int MN = gridDim.y*128*N;

    ULL acc[4][4];
    #pragma unroll
    for (int i = 0; i < 4; i++)
        #pragma unroll
        for (int j = 0; j < 4; j++) acc[i][j] = 0ULL;

    int mA = tid & 127, cA0 = tid >> 7;          // A loads: 2 per thread
    int nB = tid >> 2,  cB  = tid & 3;           // B loads: 1 per thread

    for (int k0 = kbase; k0 < kbase + KS; k0 += 16) {
        __syncthreads();
        #pragma unroll
        for (int i = 0; i < 2; i++) {
            int c = cA0 + 2*i;
            float4 v = *(const float4*)&A[(size_t)(m0+mA)*K + k0 + 4*c];
            As[(4*c+0)*132 + mA] = v.x;
            As[(4*c+1)*132 + mA] = v.y;
            As[(4*c+2)*132 + mA] = v.z;
            As[(4*c+3)*132 + mA] = v.w;
        }
        {
            float4 v = *(const float4*)&Bm[(size_t)(n0+nB)*K + k0 + 4*cB];
            *(float2*)&Bs[(4*cB+0)*136 + 2*nB] = make_float2(v.x, v.x);
            *(float2*)&Bs[(4*cB+1)*136 + 2*nB] = make_float2(v.y, v.y);
            *(float2*)&Bs[(4*cB+2)*136 + 2*nB] = make_float2(v.z, v.z);
            *(float2*)&Bs[(4*cB+3)*136 + 2*nB] = make_float2(v.w, v.w);
        }
        __syncthreads();
        #pragma unroll
        for (int kk = 0; kk < 16; kk++) {
            const ulonglong2* ap = (const ulonglong2*)&As[kk*132 + 8*ty];
            const ulonglong2* bp = (const ulonglong2*)&Bs[kk*136 + 8*tx];
            ulonglong2 a01 = ap[0], a23 = ap[1];
            ulonglong2 b01 = bp[0], b23 = bp[1];
            ULL a[4] = {a01.x, a01.y, a23.x, a23.y};
            ULL b[4] = {b01.x, b01.y, b23.x, b23.y};
            #pragma unroll
            for (int i = 0; i < 4; i++)
                #pragma unroll
                for (int j = 0; j < 4; j++)
                    acc[i][j] = ffma2(a[i], b[j], acc[i][j]);
        }
    }
    float* cp = Cp + (size_t)ks*MN;
    #pragma unroll
    for (int i = 0; i < 4; i++) {
        int m = m0 + 8*ty + 2*i;
        #pragma unroll
        for (int j = 0; j < 4; j++) {
            int nn = n0 + 4*tx + j;
            float2 v = unpack2(acc[i][j]);
            cp[(size_t)m*N + nn]     = v.x;
            cp[(size_t)(m+1)*N + nn] = v.y;
        }
    }
}

// reduce split-K partials + bias (+relu)
template<int S, int NC, bool RELU>
__global__ void k_red(const float* __restrict__ bias, float* __restrict__ C, int MN) {
    int i = blockIdx.x*256 + threadIdx.x;
    if (i >= MN) return;
    float s = bias[i % NC];
    #pragma unroll
    for (int j = 0; j < S; j++) s += g_red[(size_t)j*MN + i];
    C[i] = RELU ? fmaxf(s, 0.f) : s;
}

// ---------------- GRU: single persistent kernel, 32 steps ----------------
__global__ void k_init_h(const float* __restrict__ states) {
    int i = blockIdx.x*256 + threadIdx.x;   // < 8192
    g_h[i] = states[i];
    if (i == 0) g_bar = 0;
}

// grid 32 x 256. block b owns hh in [b*16, b*16+16).
// smem: w_s[48][512] (rows hh, 512+hh, 1024+hh) + h_s[16][514]
__global__ void k_gru(const float* __restrict__ w_hh, const float* __restrict__ masks,
                      const float* __restrict__ b_hh) {
    extern __shared__ float sm[];
    float* w_s = sm;                 // 48*512
    float* h_s = sm + 48*512;        // 16*514
    int tid = threadIdx.x, b = blockIdx.x;
    int hh0 = b*16;
    for (int idx = tid; idx < 24576; idx += 256) {
        int lr = idx >> 9, k = idx & 511;
        int grow = (lr >> 4)*512 + hh0 + (lr & 15);
        w_s[idx] = w_hh[(size_t)grow*512 + k];
    }
    int hh_l = tid >> 4, n = tid & 15;
    int hh = hh0 + hh_l;
    float br = b_hh[hh], bz = b_hh[512+hh], bn = b_hh[1024+hh];
    const float* wr = w_s + hh_l*512;
    const float* wz = w_s + (16+hh_l)*512;
    const float* wn = w_s + (32+hh_l)*512;
    const float* hp = h_s + n*514;

    for (int t = 0; t < 32; t++) {
        int row = t*16 + n;
        float gi_r = g_gi[(size_t)row*1536 + hh];
        float gi_z = g_gi[(size_t)row*1536 + 512 + hh];
        float gi_n = g_gi[(size_t)row*1536 + 1024 + hh];
        for (int idx = tid; idx < 8192; idx += 256) {
            int nn = idx >> 9, k = idx & 511;
            h_s[nn*514 + k] = g_h[idx] * masks[t*16 + nn];
        }
        __syncthreads();

        ULL ar0=0,ar1=0, az0=0,az1=0, an0=0,an1=0;
        #pragma unroll 8
        for (int k = 0; k < 512; k += 8) {
            ULL h0 = *(const ULL*)(hp+k),   h1 = *(const ULL*)(hp+k+2);
            ULL h2 = *(const ULL*)(hp+k+4), h3 = *(const ULL*)(hp+k+6);
            ulonglong2 ra = *(const ulonglong2*)(wr+k), rb = *(const ulonglong2*)(wr+k+4);
            ulonglong2 za = *(const ulonglong2*)(wz+k), zb = *(const ulonglong2*)(wz+k+4);
            ulonglong2 na = *(const ulonglong2*)(wn+k), nb = *(const ulonglong2*)(wn+k+4);
            ar0 = ffma2(ra.x, h0, ar0); ar1 = ffma2(ra.y, h1, ar1);
            az0 = ffma2(za.x, h0, az0); az1 = ffma2(za.y, h1, az1);
            an0 = ffma2(na.x, h0, an0); an1 = ffma2(na.y, h1, an1);
            ar0 = ffma2(rb.x, h2, ar0); ar1 = ffma2(rb.y, h3, ar1);
            az0 = ffma2(zb.x, h2, az0); az1 = ffma2(zb.y, h3, az1);
            an0 = ffma2(nb.x, h2, an0); an1 = ffma2(nb.y, h3, an1);
        }
        float2 u0 = unpack2(ar0), u1 = unpack2(ar1);
        float sr = br + u0.x + u0.y + u1.x + u1.y;
        u0 = unpack2(az0); u1 = unpack2(az1);
        float sz = bz + u0.x + u0.y + u1.x + u1.y;
        u0 = unpack2(an0); u1 = unpack2(an1);
        float sn = bn + u0.x + u0.y + u1.x + u1.y;

        float rg = 1.f/(1.f + expf(-(gi_r + sr)));
        float zg = 1.f/(1.f + expf(-(gi_z + sz)));
        float ng = tanhf(gi_n + rg*sn);
        float hm = hp[hh];                       // h*mask
        float hnew = (1.f - zg)*ng + zg*hm;
        g_h[n*512 + hh] = hnew;
        g_outs[(size_t)row*512 + hh] = hnew;

        __threadfence();
        __syncthreads();
        if (tid == 0) {
            atomicAdd(&g_bar, 1);
            while (atomicAdd(&g_bar, 0) < 32*(t+1)) { }
        }
        __syncthreads();
    }
}

// ---------------- heads ----------------
__global__ void k_heads(const float* __restrict__ aw, const float* __restrict__ ab,
                        const float* __restrict__ cw, const float* __restrict__ cb,
                        const int* __restrict__ action, float* __restrict__ out) {
    int wrp = threadIdx.x >> 5, lane = threadIdx.x & 31;
    int row = blockIdx.x*4 + wrp;
    const float* x = g_outs + (size_t)row*512;
    float p[7];
    #pragma unroll
    for (int j = 0; j < 7; j++) p[j] = 0.f;
    for (int k = lane; k < 512; k += 32) {
        float xv = x[k];
        #pragma unroll
        for (int j = 0; j < 6; j++) p[j] += xv * aw[j*512 + k];
        p[6] += xv * cw[k];
    }
    #pragma unroll
    for (int j = 0; j < 7; j++)
        #pragma unroll
        for (int o = 16; o > 0; o >>= 1) p[j] += __shfl_xor_sync(0xffffffffu, p[j], o);
    if (lane == 0) {
        float l[6];
        #pragma unroll
        for (int j = 0; j < 6; j++) l[j] = p[j] + ab[j];
        float v = p[6] + cb[0];
        float m = l[0];
        #pragma unroll
        for (int j = 1; j < 6; j++) m = fmaxf(m, l[j]);
        float se = 0.f;
        #pragma unroll
        for (int j = 0; j < 6; j++) se += expf(l[j] - m);
        float lse = m + logf(se);
        int a = action[row];
        float alp = 0.f;
        #pragma unroll
        for (int j = 0; j < 6; j++) if (j == a) alp = l[j] - lse;
        float ent = 0.f;
        #pragma unroll
        for (int j = 0; j < 6; j++) { float lp = l[j] - lse; ent -= expf(lp)*lp; }
        out[row] = v;
        out[512 + row] = alp;
        out[1024 + row] = ent;
    }
}

__global__ void k_states_out(float* __restrict__ out) {
    int i = blockIdx.x*256 + threadIdx.x;   // < 8192
    out[1536 + i] = g_h[i];
}

// ---------------- launch ----------------
extern "C" void kernel_launch(void* const* d_in, const int* in_sizes, int n_in,
                              void* d_out, int out_size) {
    const float* inputs   = (const float*)d_in[0];
    const float* states   = (const float*)d_in[1];
    const float* masks    = (const float*)d_in[2];
    const int*   action   = (const int*)d_in[3];
    const float* conv1_w  = (const float*)d_in[4];
    const float* conv1_b  = (const float*)d_in[5];
    const float* conv2_w  = (const float*)d_in[6];
    const float* conv2_b  = (const float*)d_in[7];
    const float* conv3_w  = (const float*)d_in[8];
    const float* conv3_b  = (const float*)d_in[9];
    const float* fc_w     = (const float*)d_in[10];
    const float* fc_b     = (const float*)d_in[11];
    const float* w_ih     = (const float*)d_in[12];
    const float* w_hh     = (const float*)d_in[13];
    const float* b_ih     = (const float*)d_in[14];
    const float* b_hh     = (const float*)d_in[15];
    const float* actor_w  = (const float*)d_in[16];
    const float* actor_b  = (const float*)d_in[17];
    const float* critic_w = (const float*)d_in[18];
    const float* critic_b = (const float*)d_in[19];
    float* out = (float*)d_out;
    (void)in_sizes; (void)n_in; (void)out_size;

    float* d_red;  cudaGetSymbolAddress((void**)&d_red, g_red);
    float* d_x3;   cudaGetSymbolAddress((void**)&d_x3, g_x3);
    float* d_fc;   cudaGetSymbolAddress((void**)&d_fc, g_fc);
    float* d_gi;   cudaGetSymbolAddress((void**)&d_gi, g_gi);

    cudaFuncSetAttribute(k_conv2, cudaFuncAttributeMaxDynamicSharedMemorySize, 80896);
    cudaFuncSetAttribute(k_conv3, cudaFuncAttributeMaxDynamicSharedMemorySize, 123904);
    cudaFuncSetAttribute(k_gru,   cudaFuncAttributeMaxDynamicSharedMemorySize, 131200);

    k_conv1<<<512, 256>>>(inputs, conv1_w, conv1_b);
    k_conv2<<<dim3(512, 2), 224, 80896>>>(conv2_w, conv2_b);
    k_conv3<<<512, 384, 123904>>>(conv3_w, conv3_b);

    // fc: M=512, N=512, K=4608, split 8
    k_gemm2<512, 4608, 8><<<dim3(8, 4, 8), 256>>>(d_x3, fc_w, d_red);
    k_red<8, 512, true><<<1024, 256>>>(fc_b, d_fc, 512*512);
    // gi: M=512, N=1536, K=512, split 2
    k_gemm2<1536, 512, 2><<<dim3(24, 4, 2), 256>>>(d_fc, w_ih, d_red);
    k_red<2, 1536, false><<<3072, 256>>>(b_ih, d_gi, 512*1536);

    k_init_h<<<32, 256>>>(states);
    k_gru<<<32, 256, 131200>>>(w_hh, masks, b_hh);

    k_heads<<<128, 128>>>(actor_w, actor_b, critic_w, critic_b, action, out);
    k_states_out<<<32, 256>>>(out);
}

// round 5
// speedup vs baseline: 1.8860x; 1.4707x over previous
#include <cuda_runtime.h>
#include <math.h>

typedef unsigned long long ULL;

// ---------------- scratch ----------------
__device__ float g_x1[512*32*30*30];     // conv1 out
__device__ float g_x2[512*64*14*14];     // conv2 out
__device__ float g_x3[512*32*12*12];     // conv3 out == fc input rows [512][4608]
__device__ float g_fc[512*512];          // fc out
__device__ float g_gi[512*1536];         // input-to-hidden gates
__device__ float g_h[16*512];            // GRU hidden
__device__ float g_outs[512*512];        // GRU outputs per (t,n)
__device__ float g_red[8*512*512];       // split-K partials
__device__ int   g_bar;                  // GRU grid barrier counter

// ---------------- f32x2 helpers ----------------
__device__ __forceinline__ ULL ffma2(ULL a, ULL b, ULL c) {
    ULL d;
    asm("fma.rn.f32x2 %0, %1, %2, %3;" : "=l"(d) : "l"(a), "l"(b), "l"(c));
    return d;
}
__device__ __forceinline__ float2 unpack2(ULL a) {
    float2 u;
    asm("mov.b64 {%0, %1}, %2;" : "=f"(u.x), "=f"(u.y) : "l"(a));
    return u;
}
__device__ __forceinline__ ULL dup2(float x) {
    ULL r;
    asm("mov.b64 %0, {%1, %1};" : "=l"(r) : "f"(x));
    return r;
}

// 8 oc-pairs x 2 spatial FFMA2 block
#define FMA16(wa,wb,wc,wd,d0,d1,A) do { \
    A[0][0]=ffma2(wa.x,d0,A[0][0]); A[0][1]=ffma2(wa.x,d1,A[0][1]); \
    A[1][0]=ffma2(wa.y,d0,A[1][0]); A[1][1]=ffma2(wa.y,d1,A[1][1]); \
    A[2][0]=ffma2(wb.x,d0,A[2][0]); A[2][1]=ffma2(wb.x,d1,A[2][1]); \
    A[3][0]=ffma2(wb.y,d0,A[3][0]); A[3][1]=ffma2(wb.y,d1,A[3][1]); \
    A[4][0]=ffma2(wc.x,d0,A[4][0]); A[4][1]=ffma2(wc.x,d1,A[4][1]); \
    A[5][0]=ffma2(wc.y,d0,A[5][0]); A[5][1]=ffma2(wc.y,d1,A[5][1]); \
    A[6][0]=ffma2(wd.x,d0,A[6][0]); A[6][1]=ffma2(wd.x,d1,A[6][1]); \
    A[7][0]=ffma2(wd.y,d0,A[7][0]); A[7][1]=ffma2(wd.y,d1,A[7][1]); } while(0)

// ---------------- conv1: [512,4,124,124] -> [512,32,30,30], 8x8 s4 ----------------
// block per image, 256 thr: och = tid>>7 (16 oc), rem: oyL = rem/15, oxp = rem%15 (2 ox).
// 4 passes of 8 oy rows.
__global__ void k_conv1(const float* __restrict__ in, const float* __restrict__ w,
                        const float* __restrict__ bias) {
    extern __shared__ float s1[];
    float* sW = s1;            // [k 256][oc 32 pad 36] = 9216
    float* sI = s1 + 9216;     // [ic 4][y 36][x 124] = 17856
    int n = blockIdx.x, tid = threadIdx.x;
    for (int i = tid; i < 8192; i += 256) {
        int oc = i >> 8, k = i & 255;
        sW[k*36 + oc] = w[i];
    }
    int och = tid >> 7, rem = tid & 127;
    bool act = rem < 120;
    int oyL = act ? rem/15 : 0, oxp = act ? rem%15 : 0;
    const float* inN = in + (size_t)n*61504;
    const float inv255 = 1.f/255.f;
    for (int p = 0; p < 4; p++) {
        int y0 = 32*p;
        int ylim = 124 - y0; if (ylim > 36) ylim = 36;
        __syncthreads();
        for (int i = tid; i < 17856; i += 256) {
            int ic = i / 4464, r2 = i - ic*4464;
            int y = r2 / 124, x = r2 - y*124;
            if (y < ylim) sI[i] = inN[ic*15376 + (y0+y)*124 + x];
        }
        __syncthreads();
        ULL acc[8][2];
        #pragma unroll
        for (int j = 0; j < 8; j++) { acc[j][0] = 0ULL; acc[j][1] = 0ULL; }
        #pragma unroll 1
        for (int ic = 0; ic < 4; ic++) {
            #pragma unroll
            for (int ky = 0; ky < 8; ky++) {
                const float4* ip = (const float4*)&sI[ic*4464 + (4*oyL+ky)*124 + 8*oxp];
                float4 i0 = ip[0], i1 = ip[1], i2 = ip[2];
                float inr[12] = {i0.x,i0.y,i0.z,i0.w, i1.x,i1.y,i1.z,i1.w, i2.x,i2.y,i2.z,i2.w};
                #pragma unroll
                for (int kx = 0; kx < 8; kx++) {
                    int k = ic*64 + ky*8 + kx;
                    const ulonglong2* wp = (const ulonglong2*)&sW[k*36 + och*16];
                    ulonglong2 wa = wp[0], wb = wp[1], wc = wp[2], wd = wp[3];
                    ULL d0 = dup2(inr[kx]), d1 = dup2(inr[kx+4]);
                    FMA16(wa, wb, wc, wd, d0, d1, acc);
                }
            }
        }
        int oy = 8*p + oyL;
        if (act && oy < 30) {
            float* op = g_x1 + (size_t)n*28800 + oy*30 + 2*oxp;
            #pragma unroll
            for (int j = 0; j < 8; j++) {
                int oc = och*16 + 2*j;
                float2 a0 = unpack2(acc[j][0]), a1 = unpack2(acc[j][1]);
                float b0 = bias[oc], b1 = bias[oc+1];
                float2 v0 = make_float2(fmaxf(a0.x*inv255 + b0, 0.f), fmaxf(a1.x*inv255 + b0, 0.f));
                float2 v1 = make_float2(fmaxf(a0.y*inv255 + b1, 0.f), fmaxf(a1.y*inv255 + b1, 0.f));
                *(float2*)&op[(size_t)oc*900]     = v0;
                *(float2*)&op[(size_t)(oc+1)*900] = v1;
            }
        }
    }
}

// ---------------- conv2: [512,32,30,30] -> [512,64,14,14], 4x4 s2 ----------------
// grid (512, 2): image, oc-half. 224 thr: ocg = tid/112 (16 oc), idx<98: oy=idx/7, oxp=idx%7.
__global__ void k_conv2(const float* __restrict__ w, const float* __restrict__ bias) {
    extern __shared__ float s2[];
    float* sW = s2;            // [k 512][oc 32 pad 36] = 18432
    float* sI = s2 + 18432;    // [ic 32][y 30][x pad 32] = 30720
    int n = blockIdx.x, h = blockIdx.y, tid = threadIdx.x;
    for (int i = tid; i < 16384; i += 224) {
        int oc = i >> 9, k = i & 511;
        sW[k*36 + oc] = w[(h*32+oc)*512 + k];
    }
    const float* src = g_x1 + (size_t)n*28800;
    for (int i = tid; i < 28800; i += 224) {
        int ic = i / 900, r = i - ic*900;
        int y = r / 30, x = r - y*30;
        sI[ic*960 + y*32 + x] = src[i];
    }
    __syncthreads();
    int ocg = tid / 112, idx = tid - ocg*112;
    bool act = idx < 98;
    int oy = act ? idx/7 : 0, oxp = act ? idx%7 : 0;
    ULL acc[8][2];
    #pragma unroll
    for (int j = 0; j < 8; j++) { acc[j][0] = 0ULL; acc[j][1] = 0ULL; }
    #pragma unroll 1
    for (int ic = 0; ic < 32; ic++) {
        #pragma unroll
        for (int ky = 0; ky < 4; ky++) {
            const float4* ip = (const float4*)&sI[ic*960 + (2*oy+ky)*32 + 4*oxp];
            float4 i0 = ip[0], i1 = ip[1];
            float inr[8] = {i0.x,i0.y,i0.z,i0.w, i1.x,i1.y,i1.z,i1.w};
            #pragma unroll
            for (int kx = 0; kx < 4; kx++) {
                int k = ic*16 + ky*4 + kx;
                const ulonglong2* wp = (const ulonglong2*)&sW[k*36 + ocg*16];
                ulonglong2 wa = wp[0], wb = wp[1], wc = wp[2], wd = wp[3];
                ULL d0 = dup2(inr[kx]), d1 = dup2(inr[kx+2]);
                FMA16(wa, wb, wc, wd, d0, d1, acc);
            }
        }
    }
    if (act) {
        float* op = g_x2 + (size_t)(n*64 + h*32)*196 + oy*14 + 2*oxp;
        #pragma unroll
        for (int j = 0; j < 8; j++) {
            int oc = ocg*16 + 2*j;
            float2 a0 = unpack2(acc[j][0]), a1 = unpack2(acc[j][1]);
            float b0 = bias[h*32 + oc], b1 = bias[h*32 + oc + 1];
            float2 v0 = make_float2(fmaxf(a0.x + b0, 0.f), fmaxf(a1.x + b0, 0.f));
            float2 v1 = make_float2(fmaxf(a0.y + b1, 0.f), fmaxf(a1.y + b1, 0.f));
            *(float2*)&op[(size_t)oc*196]     = v0;
            *(float2*)&op[(size_t)(oc+1)*196] = v1;
        }
    }
}

// ---------------- conv3: [512,64,14,14] -> [512,32,12,12], 3x3 s1 ----------------
// grid 256: 2 images per block. 288 thr: img = tid/144, r: ocg = r/72, sp: oy=sp/6, oxp=sp%6.
__global__ void k_conv3(const float* __restrict__ w, const float* __restrict__ bias) {
    extern __shared__ float s3[];
    float* sW = s3;            // [k 576][oc 32 pad 36] = 20736
    float* sI = s3 + 20736;    // [img 2][ic 64][y 14][x pad 16] = 28672
    int n0 = blockIdx.x*2, tid = threadIdx.x;
    for (int i = tid; i < 18432; i += 288) {
        int oc = i / 576, k = i - oc*576;
        sW[k*36 + oc] = w[i];
    }
    for (int i = tid; i < 25088; i += 288) {
        int img = i / 12544, r = i - img*12544;
        int ic = r / 196, r2 = r - ic*196;
        int y = r2 / 14, x = r2 - y*14;
        sI[img*14336 + ic*224 + y*16 + x] = g_x2[(size_t)(n0+img)*12544 + r];
    }
    __syncthreads();
    int img = tid / 144, r = tid - img*144;
    int ocg = r / 72, sp = r - ocg*72;
    int oy = sp / 6, oxp = sp - oy*6;
    int x0 = 2*oxp, al = x0 & ~3, o = x0 & 3;
    ULL acc[8][2];
    #pragma unroll
    for (int j = 0; j < 8; j++) { acc[j][0] = 0ULL; acc[j][1] = 0ULL; }
    const float* base = sI + img*14336;
    #pragma unroll 1
    for (int ic = 0; ic < 64; ic++) {
        #pragma unroll
        for (int ky = 0; ky < 3; ky++) {
            const float4* ip = (const float4*)&base[ic*224 + (oy+ky)*16 + al];
            float4 i0 = ip[0], i1 = ip[1];
            float inr[8] = {i0.x,i0.y,i0.z,i0.w, i1.x,i1.y,i1.z,i1.w};
            #pragma unroll
            for (int kx = 0; kx < 3; kx++) {
                int k = ic*9 + ky*3 + kx;
                const ulonglong2* wp = (const ulonglong2*)&sW[k*36 + ocg*16];
                ulonglong2 wa = wp[0], wb = wp[1], wc = wp[2], wd = wp[3];
                ULL d0 = dup2(inr[o+kx]), d1 = dup2(inr[o+1+kx]);
                FMA16(wa, wb, wc, wd, d0, d1, acc);
            }
        }
    }
    {
        float* op = g_x3 + (size_t)(n0+img)*4608 + oy*12 + 2*oxp;
        #pragma unroll
        for (int j = 0; j < 8; j++) {
            int oc = ocg*16 + 2*j;
            float2 a0 = unpack2(acc[j][0]), a1 = unpack2(acc[j][1]);
            float b0 = bias[oc], b1 = bias[oc+1];
            float2 v0 = make_float2(fmaxf(a0.x + b0, 0.f), fmaxf(a1.x + b0, 0.f));
            float2 v1 = make_float2(fmaxf(a0.y + b1, 0.f), fmaxf(a1.y + b1, 0.f));
            *(float2*)&op[(size_t)oc*144]     = v0;
            *(float2*)&op[(size_t)(oc+1)*144] = v1;
        }
    }
}

// ---------------- split-K f32x2 GEMM (unchanged) ----------------
template<int N, int K, int S>
__global__ void k_gemm2(const float* __restrict__ A, const float* __restrict__ Bm,
                        float* __restrict__ Cp) {
    const int KS = K / S;
    __shared__ __align__(16) float As[16*132];   // [k][m] transposed
    __shared__ __align__(16) float Bs[16*136];   // [k][2n] duplicated pairs
    int tid = threadIdx.x;
    int tx = tid & 15, ty = tid >> 4;
    int n0 = blockIdx.x*64, m0 = blockIdx.y*128, ks = blockIdx.z;
    int kbase = ks*KS;
    const int MN = gridDim.y*128*N;

    ULL acc[4][4];
    #pragma unroll
    for (int i = 0; i < 4; i++)
        #pragma unroll
        for (int j = 0; j < 4; j++) acc[i][j] = 0ULL;

    int mA = tid & 127, cA0 = tid >> 7;
    int nB = tid >> 2,  cB  = tid & 3;

    for (int k0 = kbase; k0 < kbase + KS; k0 += 16) {
        __syncthreads();
        #pragma unroll
        for (int i = 0; i < 2; i++) {
            int c = cA0 + 2*i;
            float4 v = *(const float4*)&A[(size_t)(m0+mA)*K + k0 + 4*c];
            As[(4*c+0)*132 + mA] = v.x;
            As[(4*c+1)*132 + mA] = v.y;
            As[(4*c+2)*132 + mA] = v.z;
            As[(4*c+3)*132 + mA] = v.w;
        }
        {
            float4 v = *(const float4*)&Bm[(size_t)(n0+nB)*K + k0 + 4*cB];
            *(float2*)&Bs[(4*cB+0)*136 + 2*nB] = make_float2(v.x, v.x);
            *(float2*)&Bs[(4*cB+1)*136 + 2*nB] = make_float2(v.y, v.y);
            *(float2*)&Bs[(4*cB+2)*136 + 2*nB] = make_float2(v.z, v.z);
            *(float2*)&Bs[(4*cB+3)*136 + 2*nB] = make_float2(v.w, v.w);
        }
        __syncthreads();
        #pragma unroll
        for (int kk = 0; kk < 16; kk++) {
            const ulonglong2* ap = (const ulonglong2*)&As[kk*132 + 8*ty];
            const ulonglong2* bp = (const ulonglong2*)&Bs[kk*136 + 8*tx];
            ulonglong2 a01 = ap[0], a23 = ap[1];
            ulonglong2 b01 = bp[0], b23 = bp[1];
            ULL a[4] = {a01.x, a01.y, a23.x, a23.y};
            ULL b[4] = {b01.x, b01.y, b23.x, b23.y};
            #pragma unroll
            for (int i = 0; i < 4; i++)
                #pragma unroll
                for (int j = 0; j < 4; j++)
                    acc[i][j] = ffma2(a[i], b[j], acc[i][j]);
        }
    }
    float* cp = Cp + (size_t)ks*MN;
    #pragma unroll
    for (int i = 0; i < 4; i++) {
        int m = m0 + 8*ty + 2*i;
        #pragma unroll
        for (int j = 0; j < 4; j++) {
            int nn = n0 + 4*tx + j;
            float2 v = unpack2(acc[i][j]);
            cp[(size_t)m*N + nn]     = v.x;
            cp[(size_t)(m+1)*N + nn] = v.y;
        }
    }
}

template<int S, int NC, bool RELU>
__global__ void k_red(const float* __restrict__ bias, float* __restrict__ C, int MN) {
    int i = blockIdx.x*256 + threadIdx.x;
    if (i >= MN) return;
    float s = bias[i % NC];
    #pragma unroll
    for (int j = 0; j < S; j++) s += g_red[(size_t)j*MN + i];
    C[i] = RELU ? fmaxf(s, 0.f) : s;
}

// ---------------- GRU: single persistent kernel, 32 steps ----------------
__global__ void k_init_h(const float* __restrict__ states) {
    int i = blockIdx.x*256 + threadIdx.x;   // < 8192
    g_h[i] = states[i];
    if (i == 0) g_bar = 0;
}

__global__ void k_gru(const float* __restrict__ w_hh, const float* __restrict__ masks,
                      const float* __restrict__ b_hh) {
    extern __shared__ float sm[];
    float* w_s = sm;                 // 48*512
    float* h_s = sm + 48*512;        // 16*514
    int tid = threadIdx.x, b = blockIdx.x;
    int hh0 = b*16;
    for (int idx = tid; idx < 24576; idx += 256) {
        int lr = idx >> 9, k = idx & 511;
        int grow = (lr >> 4)*512 + hh0 + (lr & 15);
        w_s[idx] = w_hh[(size_t)grow*512 + k];
    }
    int hh_l = tid >> 4, n = tid & 15;
    int hh = hh0 + hh_l;
    float br = b_hh[hh], bz = b_hh[512+hh], bn = b_hh[1024+hh];
    const float* wr = w_s + hh_l*512;
    const float* wz = w_s + (16+hh_l)*512;
    const float* wn = w_s + (32+hh_l)*512;
    const float* hp = h_s + n*514;

    for (int t = 0; t < 32; t++) {
        int row = t*16 + n;
        float gi_r = g_gi[(size_t)row*1536 + hh];
        float gi_z = g_gi[(size_t)row*1536 + 512 + hh];
        float gi_n = g_gi[(size_t)row*1536 + 1024 + hh];
        for (int idx = tid; idx < 8192; idx += 256) {
            int nn = idx >> 9, k = idx & 511;
            h_s[nn*514 + k] = g_h[idx] * masks[t*16 + nn];
        }
        __syncthreads();

        ULL ar0=0,ar1=0, az0=0,az1=0, an0=0,an1=0;
        #pragma unroll 8
        for (int k = 0; k < 512; k += 8) {
            ULL h0 = *(const ULL*)(hp+k),   h1 = *(const ULL*)(hp+k+2);
            ULL h2 = *(const ULL*)(hp+k+4), h3 = *(const ULL*)(hp+k+6);
            ulonglong2 ra = *(const ulonglong2*)(wr+k), rb = *(const ulonglong2*)(wr+k+4);
            ulonglong2 za = *(const ulonglong2*)(wz+k), zb = *(const ulonglong2*)(wz+k+4);
            ulonglong2 na = *(const ulonglong2*)(wn+k), nb = *(const ulonglong2*)(wn+k+4);
            ar0 = ffma2(ra.x, h0, ar0); ar1 = ffma2(ra.y, h1, ar1);
            az0 = ffma2(za.x, h0, az0); az1 = ffma2(za.y, h1, az1);
            an0 = ffma2(na.x, h0, an0); an1 = ffma2(na.y, h1, an1);
            ar0 = ffma2(rb.x, h2, ar0); ar1 = ffma2(rb.y, h3, ar1);
            az0 = ffma2(zb.x, h2, az0); az1 = ffma2(zb.y, h3, az1);
            an0 = ffma2(nb.x, h2, an0); an1 = ffma2(nb.y, h3, an1);
        }
        float2 u0 = unpack2(ar0), u1 = unpack2(ar1);
        float sr = br + u0.x + u0.y + u1.x + u1.y;
        u0 = unpack2(az0); u1 = unpack2(az1);
        float sz = bz + u0.x + u0.y + u1.x + u1.y;
        u0 = unpack2(an0); u1 = unpack2(an1);
        float sn = bn + u0.x + u0.y + u1.x + u1.y;

        float rg = 1.f/(1.f + expf(-(gi_r + sr)));
        float zg = 1.f/(1.f + expf(-(gi_z + sz)));
        float ng = tanhf(gi_n + rg*sn);
        float hm = hp[hh];
        float hnew = (1.f - zg)*ng + zg*hm;
        g_h[n*512 + hh] = hnew;
        g_outs[(size_t)row*512 + hh] = hnew;

        __threadfence();
        __syncthreads();
        if (tid == 0) {
            atomicAdd(&g_bar, 1);
            while (atomicAdd(&g_bar, 0) < 32*(t+1)) { }
        }
        __syncthreads();
    }
}

// ---------------- heads ----------------
__global__ void k_heads(const float* __restrict__ aw, const float* __restrict__ ab,
                        const float* __restrict__ cw, const float* __restrict__ cb,
                        const int* __restrict__ action, float* __restrict__ out) {
    int wrp = threadIdx.x >> 5, lane = threadIdx.x & 31;
    int row = blockIdx.x*4 + wrp;
    const float* x = g_outs + (size_t)row*512;
    float p[7];
    #pragma unroll
    for (int j = 0; j < 7; j++) p[j] = 0.f;
    for (int k = lane; k < 512; k += 32) {
        float xv = x[k];
        #pragma unroll
        for (int j = 0; j < 6; j++) p[j] += xv * aw[j*512 + k];
        p[6] += xv * cw[k];
    }
    #pragma unroll
    for (int j = 0; j < 7; j++)
        #pragma unroll
        for (int o = 16; o > 0; o >>= 1) p[j] += __shfl_xor_sync(0xffffffffu, p[j], o);
    if (lane == 0) {
        float l[6];
        #pragma unroll
        for (int j = 0; j < 6; j++) l[j] = p[j] + ab[j];
        float v = p[6] + cb[0];
        float m = l[0];
        #pragma unroll
        for (int j = 1; j < 6; j++) m = fmaxf(m, l[j]);
        float se = 0.f;
        #pragma unroll
        for (int j = 0; j < 6; j++) se += expf(l[j] - m);
        float lse = m + logf(se);
        int a = action[row];
        float alp = 0.f;
        #pragma unroll
        for (int j = 0; j < 6; j++) if (j == a) alp = l[j] - lse;
        float ent = 0.f;
        #pragma unroll
        for (int j = 0; j < 6; j++) { float lp = l[j] - lse; ent -= expf(lp)*lp; }
        out[row] = v;
        out[512 + row] = alp;
        out[1024 + row] = ent;
    }
}

__global__ void k_states_out(float* __restrict__ out) {
    int i = blockIdx.x*256 + threadIdx.x;   // < 8192
    out[1536 + i] = g_h[i];
}

// ---------------- launch ----------------
extern "C" void kernel_launch(void* const* d_in, const int* in_sizes, int n_in,
                              void* d_out, int out_size) {
    const float* inputs   = (const float*)d_in[0];
    const float* states   = (const float*)d_in[1];
    const float* masks    = (const float*)d_in[2];
    const int*   action   = (const int*)d_in[3];
    const float* conv1_w  = (const float*)d_in[4];
    const float* conv1_b  = (const float*)d_in[5];
    const float* conv2_w  = (const float*)d_in[6];
    const float* conv2_b  = (const float*)d_in[7];
    const float* conv3_w  = (const float*)d_in[8];
    const float* conv3_b  = (const float*)d_in[9];
    const float* fc_w     = (const float*)d_in[10];
    const float* fc_b     = (const float*)d_in[11];
    const float* w_ih     = (const float*)d_in[12];
    const float* w_hh     = (const float*)d_in[13];
    const float* b_ih     = (const float*)d_in[14];
    const float* b_hh     = (const float*)d_in[15];
    const float* actor_w  = (const float*)d_in[16];
    const float* actor_b  = (const float*)d_in[17];
    const float* critic_w = (const float*)d_in[18];
    const float* critic_b = (const float*)d_in[19];
    float* out = (float*)d_out;
    (void)in_sizes; (void)n_in; (void)out_size;

    float* d_red;  cudaGetSymbolAddress((void**)&d_red, g_red);
    float* d_x3;   cudaGetSymbolAddress((void**)&d_x3, g_x3);
    float* d_fc;   cudaGetSymbolAddress((void**)&d_fc, g_fc);
    float* d_gi;   cudaGetSymbolAddress((void**)&d_gi, g_gi);

    cudaFuncSetAttribute(k_conv1, cudaFuncAttributeMaxDynamicSharedMemorySize, 108288);
    cudaFuncSetAttribute(k_conv2, cudaFuncAttributeMaxDynamicSharedMemorySize, 196608);
    cudaFuncSetAttribute(k_conv3, cudaFuncAttributeMaxDynamicSharedMemorySize, 197632);
    cudaFuncSetAttribute(k_gru,   cudaFuncAttributeMaxDynamicSharedMemorySize, 131200);

    k_conv1<<<512, 256, 108288>>>(inputs, conv1_w, conv1_b);
    k_conv2<<<dim3(512, 2), 224, 196608>>>(conv2_w, conv2_b);
    k_conv3<<<256, 288, 197632>>>(conv3_w, conv3_b);

    // fc: M=512, N=512, K=4608, split 8
    k_gemm2<512, 4608, 8><<<dim3(8, 4, 8), 256>>>(d_x3, fc_w, d_red);
    k_red<8, 512, true><<<1024, 256>>>(fc_b, d_fc, 512*512);
    // gi: M=512, N=1536, K=512, split 2
    k_gemm2<1536, 512, 2><<<dim3(24, 4, 2), 256>>>(d_fc, w_ih, d_red);
    k_red<2, 1536, false><<<3072, 256>>>(b_ih, d_gi, 512*1536);

    k_init_h<<<32, 256>>>(states);
    k_gru<<<32, 256, 131200>>>(w_hh, masks, b_hh);

    k_heads<<<128, 128>>>(actor_w, actor_b, critic_w, critic_b, action, out);
    k_states_out<<<32, 256>>>(out);
}